// round 11
// baseline (speedup 1.0000x reference)
#include <cuda_runtime.h>
#include <cuda_fp16.h>
#include <cstdint>
#include <math.h>

// Problem constants (fixed by the reference setup_inputs)
#define MPTS   4096
#define NBATCH 4
#define NITERS 50
#define NSLOTS 2            // batches concurrent per launch (L2-resident)
#define GB     148          // blocks per slot -> 296 total = 2/SM on 148 SMs
#define GRID   (NSLOTS*GB)
#define NT     256
#define CRW    4            // rows per chunk (cp.async pipeline unit)
#define TPAD   152          // partial rows padded to 8*19 (pads stay zero)
#define ROWB   8192u        // bytes per K row (4096 halfs)
#define STAGEB (CRW*8192u)  // 32 KB per stage
#define DYNSM  (2*CRW*8192) // 64 KB dynamic SMEM (two stages; needs opt-in)
#define INV_N  (1.0f/4096.0f)
#define USCALE 16777216.0f  // 2^24 : u scaled into half-friendly range
#define VSCALE 4096.0f      // INV_N * 2^24 : folded into colfix division
#define SURV_THRESH 1e-5f
#define NBARS  (2 + 2*NITERS)   // grid barriers per slot per launch

// Scratch (device globals; allocation-free per harness rules).
__device__ __half g_K16[NSLOTS][(size_t)MPTS * MPTS];   // 2 x 32 MB, L2-resident
__device__ float  g_u[NSLOTS][MPTS];
__device__ float  g_v[NSLOTS][MPTS];
__device__ float  g_T[NSLOTS][TPAD][MPTS];              // partials; rows 148..151 = 0
__device__ float  g_cmax[NSLOTS][GB];
__device__ float  g_loss[NBATCH][GB][3];                // cnt, velsq, bce
struct Bar { unsigned c; unsigned pad[31]; };           // 128B separation
__device__ Bar g_bar[NSLOTS];

__device__ __forceinline__ float warpMax(float v){
    #pragma unroll
    for (int o = 16; o; o >>= 1) v = fmaxf(v, __shfl_xor_sync(0xffffffffu, v, o));
    return v;
}
__device__ __forceinline__ float warpSum(float v){
    #pragma unroll
    for (int o = 16; o; o >>= 1) v += __shfl_xor_sync(0xffffffffu, v, o);
    return v;
}
__device__ __forceinline__ float ex2(float x){
    float r; asm("ex2.approx.f32 %0, %1;" : "=f"(r) : "f"(x)); return r;
}
__device__ __forceinline__ unsigned s2u(const void* p){
    unsigned a;
    asm("{ .reg .u64 t; cvta.to.shared.u64 t, %1; cvt.u32.u64 %0, t; }"
        : "=r"(a) : "l"(p));
    return a;
}
__device__ __forceinline__ void cpa16(unsigned dst, const void* src){
    asm volatile("cp.async.cg.shared.global [%0], [%1], 16;"
                 :: "r"(dst), "l"(src));
}
#define CP_COMMIT() asm volatile("cp.async.commit_group;" ::: "memory")
#define CP_WAIT1()  asm volatile("cp.async.wait_group 1;" ::: "memory")
__device__ __forceinline__ uint4 lds128(unsigned addr){
    uint4 r;
    asm volatile("ld.shared.v4.b32 {%0,%1,%2,%3},[%4];"
                 : "=r"(r.x), "=r"(r.y), "=r"(r.z), "=r"(r.w) : "r"(addr));
    return r;
}

// Software grid barrier among the GB blocks of one slot.
__device__ __forceinline__ void gbar(int slot, unsigned &tgt){
    __syncthreads();
    if (threadIdx.x == 0){
        __threadfence();
        atomicAdd(&g_bar[slot].c, 1u);
        while (*((volatile unsigned*)&g_bar[slot].c) < tgt) __nanosleep(32);
    }
    __syncthreads();
    tgt += GB;
}

// Convert two uint4s (16 halfs) of a K row to float (final phase only).
__device__ __forceinline__ void cvt16(const uint4 &a, const uint4 &b, float *kf){
    const __half2* ha = (const __half2*)&a;
    const __half2* hb = (const __half2*)&b;
    #pragma unroll
    for (int q = 0; q < 4; q++){
        float2 f = __half22float2(ha[q]); kf[2*q]   = f.x; kf[2*q+1]   = f.y;
        float2 g = __half22float2(hb[q]); kf[8+2*q] = g.x; kf[8+2*q+1] = g.y;
    }
}

// ---------------------------------------------------------------------------
// Persistent kernel: 2 batch slots of 148 blocks each. Sinkhorn iteration is
// a cp.async double-buffered pipeline of 4-row chunks: each thread async-
// copies exactly the two 16B K segments it consumes into SMEM (producer ==
// consumer, so per-thread wait_group is the only sync the copies need), pass
// A and pass B both read the SMEM stage (K hits L2 once per iteration), and
// prefetch runs 2 chunks ahead -- across syncs, colfix and grid barriers --
// so the memory pipe never drains.
// ---------------------------------------------------------------------------
__global__ void __launch_bounds__(NT, 2) k_persist(
        const float* __restrict__ x0p, const float* __restrict__ xgp,
        const float* __restrict__ vpp, const float* __restrict__ alp,
        int b0, unsigned base)
{
    extern __shared__ char dynsm[];         // 64 KB: two 4-row K stages
    int t = threadIdx.x, warp = t >> 5, lane = t & 31;
    int slot = (blockIdx.x >= GB) ? 1 : 0;
    int blk  = blockIdx.x - slot * GB;
    const float* x0 = x0p + (size_t)slot * MPTS * 3;
    const float* xg = xgp + (size_t)slot * MPTS * 3;
    const float* vp = vpp + (size_t)slot * MPTS * 3;
    const float* al = alp + (size_t)slot * MPTS;
    __half* Kh = g_K16[slot];

    __shared__ float red[CRW][NT];          // per-row dot partials (4 KB)
    __shared__ float su[CRW];               // scaled u' per row
    __shared__ float sr8[8];
    __shared__ float s_scalar;
    __shared__ float smx[8];
    __shared__ int   smi[8];

    unsigned tgt = base + GB;
    int rstart = (blk * MPTS) / GB;
    int rend   = ((blk + 1) * MPTS) / GB;   // 27 or 28 rows

    unsigned sK   = s2u(dynsm);             // stage s at sK + s*STAGEB
    unsigned tOff = 16u * (unsigned)t;      // this thread's segment-0 offset

    // Thread t owns columns j = 8t..8t+7 and 2048+8t..2048+8t+7.
    {
        float gx[16], gy[16], gz[16];
        #pragma unroll
        for (int h = 0; h < 2; h++){
            const float* bg = xg + (size_t)h * 2048 * 3 + 24 * t;
            #pragma unroll
            for (int c = 0; c < 8; c++){
                gx[8*h+c] = bg[3*c]; gy[8*h+c] = bg[3*c+1]; gz[8*h+c] = bg[3*c+2];
            }
        }

        // ---- Phase 0: block-local cost max -------------------------------
        float mx = 0.f;
        for (int i = rstart; i < rend; i++){
            float ax = x0[3*i], ay = x0[3*i+1], az = x0[3*i+2];
            #pragma unroll
            for (int c = 0; c < 16; c++){
                float dx = ax-gx[c], dy = ay-gy[c], dz = az-gz[c];
                mx = fmaxf(mx, dx*dx + dy*dy + dz*dz);
            }
        }
        mx = warpMax(mx);
        if (lane == 0) sr8[warp] = mx;
        __syncthreads();
        if (t == 0){
            float m = sr8[0];
            #pragma unroll
            for (int w = 1; w < 8; w++) m = fmaxf(m, sr8[w]);
            g_cmax[slot][blk] = m;
        }
        gbar(slot, tgt);

        // ---- Phase 1: global max -> scale; K16 = 2^4*exp(-C/(reg*cmax)) --
        float mc = (t < GB) ? __ldcg(&g_cmax[slot][t]) : 0.f;
        mc = warpMax(mc);
        if (lane == 0) sr8[warp] = mc;
        __syncthreads();
        if (t == 0){
            float m = sr8[0];
            #pragma unroll
            for (int w = 1; w < 8; w++) m = fmaxf(m, sr8[w]);
            s_scalar = -1.44269504088896340736f / (0.1f * m);
        }
        __syncthreads();
        float scale = s_scalar;
        for (int i = rstart; i < rend; i++){
            float ax = x0[3*i], ay = x0[3*i+1], az = x0[3*i+2];
            __half2 hk[8];
            #pragma unroll
            for (int c = 0; c < 16; c += 2){
                float dx = ax-gx[c],   dy = ay-gy[c],   dz = az-gz[c];
                float e0 = ex2(fmaf(dx*dx + dy*dy + dz*dz, scale, 4.0f));
                dx = ax-gx[c+1]; dy = ay-gy[c+1]; dz = az-gz[c+1];
                float e1 = ex2(fmaf(dx*dx + dy*dy + dz*dz, scale, 4.0f));
                hk[c/2] = __floats2half2_rn(e0, e1);
            }
            uint4* Krow = (uint4*)(Kh + (size_t)i * MPTS);
            Krow[t]       = *(uint4*)&hk[0];
            Krow[256 + t] = *(uint4*)&hk[4];
        }
        if (blk == 0){
            #pragma unroll
            for (int q = 0; q < 16; q++) g_v[slot][t + 256*q] = 1.0f;
        }
    }
    gbar(slot, tgt);

    // ---- Phase 2: 50 Sinkhorn iterations (cp.async pipeline) -------------
    // Prefetch cursor: pf_ib = next chunk row base (wraps over [rstart,rend)).
    // Stages strictly alternate; compute stage cst tracks the FIFO of groups.
    int pf_ib = rstart;
    unsigned cst = 0;                       // stage of next compute chunk
    {   // preamble: 2 groups in flight (stages 0 then 1)
        unsigned pst = 0;
        #pragma unroll
        for (int pre = 0; pre < 2; pre++){
            unsigned sb = sK + pst * STAGEB + tOff;
            #pragma unroll
            for (int r = 0; r < CRW; r++){
                if (pf_ib + r < rend){
                    const char* src = (const char*)(Kh + (size_t)(pf_ib + r) * MPTS) + tOff;
                    cpa16(sb + (unsigned)r * ROWB, src);
                    cpa16(sb + (unsigned)r * ROWB + 4096u, src + 4096);
                }
            }
            CP_COMMIT();
            pf_ib += CRW; if (pf_ib >= rend) pf_ib = rstart;
            pst ^= 1u;
        }
    }

    for (int it = 0; it < NITERS; it++){
        // load v (cross-block -> L2) and convert to half2 lanes
        __half2 vh[8];
        {
            float4 v0 = __ldcg((const float4*)(g_v[slot] + 8*t));
            float4 v1 = __ldcg((const float4*)(g_v[slot] + 8*t + 4));
            float4 v2 = __ldcg((const float4*)(g_v[slot] + 2048 + 8*t));
            float4 v3 = __ldcg((const float4*)(g_v[slot] + 2048 + 8*t + 4));
            vh[0] = __floats2half2_rn(v0.x, v0.y); vh[1] = __floats2half2_rn(v0.z, v0.w);
            vh[2] = __floats2half2_rn(v1.x, v1.y); vh[3] = __floats2half2_rn(v1.z, v1.w);
            vh[4] = __floats2half2_rn(v2.x, v2.y); vh[5] = __floats2half2_rn(v2.z, v2.w);
            vh[6] = __floats2half2_rn(v3.x, v3.y); vh[7] = __floats2half2_rn(v3.z, v3.w);
        }
        const __half2 hz = __floats2half2_rn(0.f, 0.f);
        float Tacc[16];
        #pragma unroll
        for (int c = 0; c < 16; c++) Tacc[c] = 0.f;

        #pragma unroll 1
        for (int ib = rstart; ib < rend; ib += CRW){
            unsigned sb = sK + cst * STAGEB + tOff;
            CP_WAIT1();                     // this chunk's group complete
            // ---- Pass A: row dots from SMEM stage
            #pragma unroll
            for (int r = 0; r < CRW; r++){
                if (ib + r < rend){
                    uint4 ka = lds128(sb + (unsigned)r * ROWB);
                    uint4 kb = lds128(sb + (unsigned)r * ROWB + 4096u);
                    const __half2* a2 = (const __half2*)&ka;
                    const __half2* b2 = (const __half2*)&kb;
                    __half2 acc = hz;
                    #pragma unroll
                    for (int q = 0; q < 4; q++) acc = __hfma2(a2[q], vh[q],   acc);
                    #pragma unroll
                    for (int q = 0; q < 4; q++) acc = __hfma2(b2[q], vh[4+q], acc);
                    float2 fv = __half22float2(acc);
                    red[r][t] = fv.x + fv.y;
                }
            }
            __syncthreads();
            // ---- Reduce: warp w handles row w (4 rows in parallel)
            if (warp < CRW && ib + warp < rend){
                float S = 0.f;
                #pragma unroll
                for (int q = 0; q < 8; q++) S += red[warp][lane + 32*q];
                S = warpSum(S);
                if (lane == 0){
                    float u = INV_N / S;
                    g_u[slot][ib + warp] = u;
                    su[warp] = u * USCALE;
                }
            }
            __syncthreads();
            // ---- Pass B: same SMEM stage, accumulate column partials
            {
                __half2 Tsub[8];
                #pragma unroll
                for (int q = 0; q < 8; q++) Tsub[q] = hz;
                #pragma unroll
                for (int r = 0; r < CRW; r++){
                    if (ib + r < rend){
                        uint4 ka = lds128(sb + (unsigned)r * ROWB);
                        uint4 kb = lds128(sb + (unsigned)r * ROWB + 4096u);
                        const __half2* a2 = (const __half2*)&ka;
                        const __half2* b2 = (const __half2*)&kb;
                        __half2 uh = __float2half2_rn(su[r]);
                        #pragma unroll
                        for (int q = 0; q < 4; q++){
                            Tsub[q]   = __hfma2(a2[q], uh, Tsub[q]);
                            Tsub[4+q] = __hfma2(b2[q], uh, Tsub[4+q]);
                        }
                    }
                }
                #pragma unroll
                for (int q = 0; q < 8; q++){
                    float2 fv = __half22float2(Tsub[q]);
                    Tacc[2*q]   += fv.x;
                    Tacc[2*q+1] += fv.y;
                }
            }
            // ---- Prefetch (this chunk + 2) into the stage just consumed.
            // Safe: each thread overwrites only the bytes it itself read.
            {
                #pragma unroll
                for (int r = 0; r < CRW; r++){
                    if (pf_ib + r < rend){
                        const char* src = (const char*)(Kh + (size_t)(pf_ib + r) * MPTS) + tOff;
                        cpa16(sb + (unsigned)r * ROWB, src);
                        cpa16(sb + (unsigned)r * ROWB + 4096u, src + 4096);
                    }
                }
                CP_COMMIT();
                pf_ib += CRW; if (pf_ib >= rend) pf_ib = rstart;
            }
            cst ^= 1u;
        }

        // store column partials (fp32, scaled by 2^24 via u')
        float4* Tp = (float4*)&g_T[slot][blk][0];
        Tp[2*t]       = make_float4(Tacc[0],  Tacc[1],  Tacc[2],  Tacc[3]);
        Tp[2*t+1]     = make_float4(Tacc[4],  Tacc[5],  Tacc[6],  Tacc[7]);
        Tp[512+2*t]   = make_float4(Tacc[8],  Tacc[9],  Tacc[10], Tacc[11]);
        Tp[512+2*t+1] = make_float4(Tacc[12], Tacc[13], Tacc[14], Tacc[15]);
        gbar(slot, tgt);

        // Column fix: block owns cols [rstart,rend); col = rstart + (t>>3),
        // octant q=t&7 sums partial rows [19q, 19q+19) (rows 148..151 are 0).
        {
            int c = rstart + (t >> 3);
            int q = t & 7;
            float s = 0.f;
            if (c < rend){
                #pragma unroll
                for (int p = 0; p < 19; p++) s += __ldcg(&g_T[slot][19*q + p][c]);
            }
            s += __shfl_xor_sync(0xffffffffu, s, 1);
            s += __shfl_xor_sync(0xffffffffu, s, 2);
            s += __shfl_xor_sync(0xffffffffu, s, 4);
            if (q == 0 && c < rend) g_v[slot][c] = VSCALE / s;
        }
        gbar(slot, tgt);
    }

    // ---- Phase 3: argmax of pi = u*K*v, survival, loss partials ----------
    {
        float vr[16];
        {
            float4 v0 = __ldcg((const float4*)(g_v[slot] + 8*t));
            float4 v1 = __ldcg((const float4*)(g_v[slot] + 8*t + 4));
            float4 v2 = __ldcg((const float4*)(g_v[slot] + 2048 + 8*t));
            float4 v3 = __ldcg((const float4*)(g_v[slot] + 2048 + 8*t + 4));
            vr[0]=v0.x; vr[1]=v0.y; vr[2]=v0.z;  vr[3]=v0.w;
            vr[4]=v1.x; vr[5]=v1.y; vr[6]=v1.z;  vr[7]=v1.w;
            vr[8]=v2.x; vr[9]=v2.y; vr[10]=v2.z; vr[11]=v2.w;
            vr[12]=v3.x; vr[13]=v3.y; vr[14]=v3.z; vr[15]=v3.w;
        }
        float cnt = 0.f, velsq = 0.f, bce = 0.f;   // thread 0 accumulates
        for (int i = rstart; i < rend; i++){
            const uint4* Kr = (const uint4*)(Kh + (size_t)i * MPTS);
            uint4 ka = Kr[t], kb = Kr[256 + t];
            float kf[16];
            cvt16(ka, kb, kf);
            float m = -1.f; int mi = 0;
            #pragma unroll
            for (int c = 0; c < 16; c++){
                float p = kf[c] * vr[c];
                int j = (c < 8) ? (8*t + c) : (2048 + 8*t + c - 8);
                if (p > m){ m = p; mi = j; }
            }
            #pragma unroll
            for (int o = 16; o; o >>= 1){
                float om = __shfl_xor_sync(0xffffffffu, m, o);
                int   oi = __shfl_xor_sync(0xffffffffu, mi, o);
                if (om > m || (om == m && oi < mi)){ m = om; mi = oi; }
            }
            if (lane == 0){ smx[warp] = m; smi[warp] = mi; }
            __syncthreads();
            if (t == 0){
                #pragma unroll
                for (int w = 1; w < 8; w++){
                    if (smx[w] > m || (smx[w] == m && smi[w] < mi)){
                        m = smx[w]; mi = smi[w];
                    }
                }
                float p = g_u[slot][i] * m;
                float a_i = al[i];
                float sp = fmaxf(a_i, 0.f) + log1pf(expf(-fabsf(a_i)));
                bce += sp;
                if (p > SURV_THRESH){
                    cnt += 1.f;
                    bce -= a_i;
                    #pragma unroll
                    for (int d = 0; d < 3; d++){
                        float vt = xg[3*mi + d] - x0[3*i + d];
                        float df = vp[3*i + d] - vt;
                        velsq = fmaf(df, df, velsq);
                    }
                }
            }
            __syncthreads();
        }
        if (t == 0){
            g_loss[b0 + slot][blk][0] = cnt;
            g_loss[b0 + slot][blk][1] = velsq;
            g_loss[b0 + slot][blk][2] = bce;
        }
    }
}

// ---------------------------------------------------------------------------
// Final reduction; also resets the barrier counters for the next replay
// (counters start at 0 from static init; every kernel_launch ends here).
__global__ void __launch_bounds__(NT) k_loss(float* __restrict__ out){
    int t = threadIdx.x;
    if (t < NSLOTS) g_bar[t].c = 0u;
    float cnt = 0.f, velsq = 0.f, bce = 0.f;
    for (int idx = t; idx < NBATCH * GB; idx += NT){
        int b = idx / GB, p = idx % GB;
        cnt   += g_loss[b][p][0];
        velsq += g_loss[b][p][1];
        bce   += g_loss[b][p][2];
    }
    cnt = warpSum(cnt); velsq = warpSum(velsq); bce = warpSum(bce);
    __shared__ float sc[8], sv[8], sb2[8];
    if ((t & 31) == 0){ sc[t>>5] = cnt; sv[t>>5] = velsq; sb2[t>>5] = bce; }
    __syncthreads();
    if (t == 0){
        float C = 0.f, V = 0.f, Bc = 0.f;
        #pragma unroll
        for (int w = 0; w < 8; w++){ C += sc[w]; V += sv[w]; Bc += sb2[w]; }
        float denom = fmaxf(C, 1.f);
        out[0] = V / denom + Bc / (float)(NBATCH * MPTS);
    }
}

// ---------------------------------------------------------------------------
extern "C" void kernel_launch(void* const* d_in, const int* in_sizes, int n_in,
                              void* d_out, int out_size){
    const float* x0 = (const float*)d_in[0];   // (B, M, 3)
    const float* xg = (const float*)d_in[1];   // (B, K, 3)
    const float* vp = (const float*)d_in[2];   // (B, M, 3)
    const float* al = (const float*)d_in[3];   // (B, M, 1)
    (void)in_sizes; (void)n_in; (void)out_size;

    // Opt-in for >48KB (static+dynamic) SMEM. Unconditional (no static
    // guards); not a stream op, so graph-capture-safe; not an allocation.
    cudaFuncSetAttribute(k_persist,
                         cudaFuncAttributeMaxDynamicSharedMemorySize, DYNSM);

    for (int l = 0; l < NBATCH / NSLOTS; l++){
        int b0 = l * NSLOTS;
        k_persist<<<GRID, NT, DYNSM>>>(x0 + (size_t)b0 * MPTS * 3,
                                       xg + (size_t)b0 * MPTS * 3,
                                       vp + (size_t)b0 * MPTS * 3,
                                       al + (size_t)b0 * MPTS,
                                       b0, (unsigned)(l * NBARS * GB));
    }
    k_loss<<<1, NT>>>((float*)d_out);
}

// round 12
// speedup vs baseline: 1.1116x; 1.1116x over previous
#include <cuda_runtime.h>
#include <cuda_fp16.h>
#include <cstdint>
#include <math.h>

// Problem constants (fixed by the reference setup_inputs)
#define MPTS   4096
#define NBATCH 4
#define NITERS 50
#define NSLOTS 2            // batches concurrent per launch (L2-resident: 64MB)
#define GB     148          // blocks per slot -> 296 total = 2/SM on 148 SMs
#define GRID   (NSLOTS*GB)
#define NT     256
#define CR     8            // rows per full chunk
#define NFULL  3            // full chunks per block (27|28 rows -> 3 full + tail)
#define TPAD   152          // partial rows padded to 8*19 (pads stay zero)
#define INV_N  (1.0f/4096.0f)
#define USCALE 16777216.0f  // 2^24 : u scaled into half-friendly range
#define VSCALE 4096.0f      // INV_N * 2^24 : folded into colfix division
#define SURV_THRESH 1e-5f
#define NBARS  (2 + 2*NITERS)   // grid barriers per slot per launch

// Scratch (device globals; allocation-free per harness rules).
__device__ __half g_K16[NSLOTS][(size_t)MPTS * MPTS];   // 2 x 32 MB, L2-resident
__device__ float  g_u[NSLOTS][MPTS];
__device__ float  g_v[NSLOTS][MPTS];
__device__ float  g_T[NSLOTS][TPAD][MPTS];              // partials; rows 148..151 = 0
__device__ float  g_cmax[NSLOTS][GB];
__device__ float  g_loss[NBATCH][GB][3];                // cnt, velsq, bce
struct Bar { unsigned c; unsigned pad[31]; };           // 128B separation
__device__ Bar g_bar[NSLOTS];

__device__ __forceinline__ float warpMax(float v){
    #pragma unroll
    for (int o = 16; o; o >>= 1) v = fmaxf(v, __shfl_xor_sync(0xffffffffu, v, o));
    return v;
}
__device__ __forceinline__ float warpSum(float v){
    #pragma unroll
    for (int o = 16; o; o >>= 1) v += __shfl_xor_sync(0xffffffffu, v, o);
    return v;
}
__device__ __forceinline__ float ex2(float x){
    float r; asm("ex2.approx.f32 %0, %1;" : "=f"(r) : "f"(x)); return r;
}

// Software grid barrier among the GB blocks of one slot.
__device__ __forceinline__ void gbar(int slot, unsigned &tgt){
    __syncthreads();
    if (threadIdx.x == 0){
        __threadfence();
        atomicAdd(&g_bar[slot].c, 1u);
        while (*((volatile unsigned*)&g_bar[slot].c) < tgt) __nanosleep(32);
    }
    __syncthreads();
    tgt += GB;
}

// Convert two uint4s (16 halfs) of a K row to float (final phase only).
__device__ __forceinline__ void cvt16(const uint4 &a, const uint4 &b, float *kf){
    const __half2* ha = (const __half2*)&a;
    const __half2* hb = (const __half2*)&b;
    #pragma unroll
    for (int q = 0; q < 4; q++){
        float2 f = __half22float2(ha[q]); kf[2*q]   = f.x; kf[2*q+1]   = f.y;
        float2 g = __half22float2(hb[q]); kf[8+2*q] = g.x; kf[8+2*q+1] = g.y;
    }
}

// ---------------------------------------------------------------------------
// Persistent kernel: 2 batch slots of 148 blocks each (one block of each slot
// per SM). Phases per slot: cmax -> exp(K16) -> 50x(rowpass -> colfix) ->
// argmax/loss partials. Rowpass = R7 structure (HFMA2, unconditional 8-row
// chunks). Colfix rewritten: warp w sums partial rows [19w,19w+19) with
// lane-per-column (coalesced; the old octant scheme hit ~32 sectors/warp-load
// = ~8x traffic amplification -> ~38 MB/iter hidden L2 traffic).
// ---------------------------------------------------------------------------
__global__ void __launch_bounds__(NT, 2) k_persist(
        const float* __restrict__ x0p, const float* __restrict__ xgp,
        const float* __restrict__ vpp, const float* __restrict__ alp,
        int b0, unsigned base)
{
    int t = threadIdx.x, warp = t >> 5, lane = t & 31;
    int slot = (blockIdx.x >= GB) ? 1 : 0;
    int blk  = blockIdx.x - slot * GB;
    const float* x0 = x0p + (size_t)slot * MPTS * 3;
    const float* xg = xgp + (size_t)slot * MPTS * 3;
    const float* vp = vpp + (size_t)slot * MPTS * 3;
    const float* al = alp + (size_t)slot * MPTS;
    __half* Kh = g_K16[slot];

    __shared__ float   red[2][CR][NT];      // row-sum partials (parity buffered)
    __shared__ __half2 su[2][CR];           // scaled u' per row, as half2
    __shared__ float   sr8[8];
    __shared__ float   s_scalar;
    __shared__ float   smx[8];
    __shared__ int     smi[8];
    __shared__ float   sB[8][33];           // colfix transpose buffer

    unsigned tgt = base + GB;
    int rstart = (blk * MPTS) / GB;
    int rend   = ((blk + 1) * MPTS) / GB;   // 27 or 28 rows
    int ncols  = rend - rstart;

    // Thread t owns columns j = 8t..8t+7 and 2048+8t..2048+8t+7.
    {
        float gx[16], gy[16], gz[16];
        #pragma unroll
        for (int h = 0; h < 2; h++){
            const float* bg = xg + (size_t)h * 2048 * 3 + 24 * t;
            #pragma unroll
            for (int c = 0; c < 8; c++){
                gx[8*h+c] = bg[3*c]; gy[8*h+c] = bg[3*c+1]; gz[8*h+c] = bg[3*c+2];
            }
        }

        // ---- Phase 0: block-local cost max -------------------------------
        float mx = 0.f;
        for (int i = rstart; i < rend; i++){
            float ax = x0[3*i], ay = x0[3*i+1], az = x0[3*i+2];
            #pragma unroll
            for (int c = 0; c < 16; c++){
                float dx = ax-gx[c], dy = ay-gy[c], dz = az-gz[c];
                mx = fmaxf(mx, dx*dx + dy*dy + dz*dz);
            }
        }
        mx = warpMax(mx);
        if (lane == 0) sr8[warp] = mx;
        __syncthreads();
        if (t == 0){
            float m = sr8[0];
            #pragma unroll
            for (int w = 1; w < 8; w++) m = fmaxf(m, sr8[w]);
            g_cmax[slot][blk] = m;
        }
        gbar(slot, tgt);

        // ---- Phase 1: global max -> scale; K16 = 2^4*exp(-C/(reg*cmax)) --
        float mc = (t < GB) ? __ldcg(&g_cmax[slot][t]) : 0.f;
        mc = warpMax(mc);
        if (lane == 0) sr8[warp] = mc;
        __syncthreads();
        if (t == 0){
            float m = sr8[0];
            #pragma unroll
            for (int w = 1; w < 8; w++) m = fmaxf(m, sr8[w]);
            s_scalar = -1.44269504088896340736f / (0.1f * m);
        }
        __syncthreads();
        float scale = s_scalar;
        for (int i = rstart; i < rend; i++){
            float ax = x0[3*i], ay = x0[3*i+1], az = x0[3*i+2];
            __half2 hk[8];
            #pragma unroll
            for (int c = 0; c < 16; c += 2){
                float dx = ax-gx[c],   dy = ay-gy[c],   dz = az-gz[c];
                float e0 = ex2(fmaf(dx*dx + dy*dy + dz*dz, scale, 4.0f));
                dx = ax-gx[c+1]; dy = ay-gy[c+1]; dz = az-gz[c+1];
                float e1 = ex2(fmaf(dx*dx + dy*dy + dz*dz, scale, 4.0f));
                hk[c/2] = __floats2half2_rn(e0, e1);
            }
            uint4* Krow = (uint4*)(Kh + (size_t)i * MPTS);
            Krow[t]       = *(uint4*)&hk[0];
            Krow[256 + t] = *(uint4*)&hk[4];
        }
        if (blk == 0){
            #pragma unroll
            for (int q = 0; q < 16; q++) g_v[slot][t + 256*q] = 1.0f;
        }
    }
    gbar(slot, tgt);

    // ---- Phase 2: 50 Sinkhorn iterations (HFMA2 inner loops) -------------
    for (int it = 0; it < NITERS; it++){
        // load v (cross-block -> L2) and convert to half2 lanes
        __half2 vh[8];
        {
            float4 v0 = __ldcg((const float4*)(g_v[slot] + 8*t));
            float4 v1 = __ldcg((const float4*)(g_v[slot] + 8*t + 4));
            float4 v2 = __ldcg((const float4*)(g_v[slot] + 2048 + 8*t));
            float4 v3 = __ldcg((const float4*)(g_v[slot] + 2048 + 8*t + 4));
            vh[0] = __floats2half2_rn(v0.x, v0.y); vh[1] = __floats2half2_rn(v0.z, v0.w);
            vh[2] = __floats2half2_rn(v1.x, v1.y); vh[3] = __floats2half2_rn(v1.z, v1.w);
            vh[4] = __floats2half2_rn(v2.x, v2.y); vh[5] = __floats2half2_rn(v2.z, v2.w);
            vh[6] = __floats2half2_rn(v3.x, v3.y); vh[7] = __floats2half2_rn(v3.z, v3.w);
        }
        float Tacc[16];
        #pragma unroll
        for (int c = 0; c < 16; c++) Tacc[c] = 0.f;

        const __half2 hz = __floats2half2_rn(0.f, 0.f);

        // ---- 3 full chunks of 8 rows: unconditional, front-batched loads
        #pragma unroll 1
        for (int f = 0; f < NFULL; f++){
            int ib = rstart + f * CR;
            int par = f & 1;
            // Pass A: 8 independent row sums in half2, no predicates, no syncs
            #pragma unroll
            for (int r = 0; r < CR; r++){
                const uint4* Kr = (const uint4*)(Kh + (size_t)(ib + r) * MPTS);
                uint4 ka = Kr[t], kb = Kr[256 + t];
                const __half2* a2 = (const __half2*)&ka;
                const __half2* b2 = (const __half2*)&kb;
                __half2 acc = hz;
                #pragma unroll
                for (int q = 0; q < 4; q++) acc = __hfma2(a2[q], vh[q],   acc);
                #pragma unroll
                for (int q = 0; q < 4; q++) acc = __hfma2(b2[q], vh[4+q], acc);
                float2 fv = __half22float2(acc);
                red[par][r][t] = fv.x + fv.y;
            }
            __syncthreads();
            // Block reduce: warp w reduces row w (8 rows in parallel)
            {
                float S = 0.f;
                #pragma unroll
                for (int q = 0; q < 8; q++) S += red[par][warp][lane + 32*q];
                S = warpSum(S);
                if (lane == 0){
                    float u = INV_N / S;
                    g_u[slot][ib + warp] = u;
                    su[par][warp] = __float2half2_rn(u * USCALE);
                }
            }
            __syncthreads();
            // Pass B: re-read same rows (L1-hot); chunk subtotal in half2
            {
                __half2 Tsub[8];
                #pragma unroll
                for (int q = 0; q < 8; q++) Tsub[q] = hz;
                #pragma unroll
                for (int r = 0; r < CR; r++){
                    const uint4* Kr = (const uint4*)(Kh + (size_t)(ib + r) * MPTS);
                    uint4 ka = Kr[t], kb = Kr[256 + t];
                    const __half2* a2 = (const __half2*)&ka;
                    const __half2* b2 = (const __half2*)&kb;
                    __half2 uh = su[par][r];
                    #pragma unroll
                    for (int q = 0; q < 4; q++){
                        Tsub[q]   = __hfma2(a2[q], uh, Tsub[q]);
                        Tsub[4+q] = __hfma2(b2[q], uh, Tsub[4+q]);
                    }
                }
                #pragma unroll
                for (int q = 0; q < 8; q++){
                    float2 fv = __half22float2(Tsub[q]);
                    Tacc[2*q]   += fv.x;
                    Tacc[2*q+1] += fv.y;
                }
            }
        }

        // ---- tail chunk: nr = 3 or 4 rows, predicated
        {
            int ib = rstart + NFULL * CR;
            int nr = rend - ib;
            int par = NFULL & 1;
            #pragma unroll
            for (int r = 0; r < 4; r++){
                if (r < nr){
                    const uint4* Kr = (const uint4*)(Kh + (size_t)(ib + r) * MPTS);
                    uint4 ka = Kr[t], kb = Kr[256 + t];
                    const __half2* a2 = (const __half2*)&ka;
                    const __half2* b2 = (const __half2*)&kb;
                    __half2 acc = hz;
                    #pragma unroll
                    for (int q = 0; q < 4; q++) acc = __hfma2(a2[q], vh[q],   acc);
                    #pragma unroll
                    for (int q = 0; q < 4; q++) acc = __hfma2(b2[q], vh[4+q], acc);
                    float2 fv = __half22float2(acc);
                    red[par][r][t] = fv.x + fv.y;
                }
            }
            __syncthreads();
            if (warp < nr){
                float S = 0.f;
                #pragma unroll
                for (int q = 0; q < 8; q++) S += red[par][warp][lane + 32*q];
                S = warpSum(S);
                if (lane == 0){
                    float u = INV_N / S;
                    g_u[slot][ib + warp] = u;
                    su[par][warp] = __float2half2_rn(u * USCALE);
                }
            }
            __syncthreads();
            {
                __half2 Tsub[8];
                #pragma unroll
                for (int q = 0; q < 8; q++) Tsub[q] = hz;
                #pragma unroll
                for (int r = 0; r < 4; r++){
                    if (r < nr){
                        const uint4* Kr = (const uint4*)(Kh + (size_t)(ib + r) * MPTS);
                        uint4 ka = Kr[t], kb = Kr[256 + t];
                        const __half2* a2 = (const __half2*)&ka;
                        const __half2* b2 = (const __half2*)&kb;
                        __half2 uh = su[par][r];
                        #pragma unroll
                        for (int q = 0; q < 4; q++){
                            Tsub[q]   = __hfma2(a2[q], uh, Tsub[q]);
                            Tsub[4+q] = __hfma2(b2[q], uh, Tsub[4+q]);
                        }
                    }
                }
                #pragma unroll
                for (int q = 0; q < 8; q++){
                    float2 fv = __half22float2(Tsub[q]);
                    Tacc[2*q]   += fv.x;
                    Tacc[2*q+1] += fv.y;
                }
            }
        }

        // store column partials (fp32, scaled by 2^24 via u')
        float4* Tp = (float4*)&g_T[slot][blk][0];
        Tp[2*t]       = make_float4(Tacc[0],  Tacc[1],  Tacc[2],  Tacc[3]);
        Tp[2*t+1]     = make_float4(Tacc[4],  Tacc[5],  Tacc[6],  Tacc[7]);
        Tp[512+2*t]   = make_float4(Tacc[8],  Tacc[9],  Tacc[10], Tacc[11]);
        Tp[512+2*t+1] = make_float4(Tacc[12], Tacc[13], Tacc[14], Tacc[15]);
        gbar(slot, tgt);

        // Column fix (coalesced): warp w sums partial rows [19w, 19w+19) at
        // column rstart+lane (consecutive lanes -> consecutive addresses),
        // then an 8-way SMEM combine. Rows 148..151 are zero pads.
        {
            float s = 0.f;
            if (lane < ncols){
                int c = rstart + lane;
                #pragma unroll
                for (int p = 0; p < 19; p++)
                    s += __ldcg(&g_T[slot][19*warp + p][c]);
            }
            sB[warp][lane] = s;
            __syncthreads();
            if (t < 32 && lane < ncols){
                float T = 0.f;
                #pragma unroll
                for (int g = 0; g < 8; g++) T += sB[g][lane];
                g_v[slot][rstart + lane] = VSCALE / T;
            }
        }
        gbar(slot, tgt);
    }

    // ---- Phase 3: argmax of pi = u*K*v, survival, loss partials ----------
    {
        float vr[16];
        {
            float4 v0 = __ldcg((const float4*)(g_v[slot] + 8*t));
            float4 v1 = __ldcg((const float4*)(g_v[slot] + 8*t + 4));
            float4 v2 = __ldcg((const float4*)(g_v[slot] + 2048 + 8*t));
            float4 v3 = __ldcg((const float4*)(g_v[slot] + 2048 + 8*t + 4));
            vr[0]=v0.x; vr[1]=v0.y; vr[2]=v0.z;  vr[3]=v0.w;
            vr[4]=v1.x; vr[5]=v1.y; vr[6]=v1.z;  vr[7]=v1.w;
            vr[8]=v2.x; vr[9]=v2.y; vr[10]=v2.z; vr[11]=v2.w;
            vr[12]=v3.x; vr[13]=v3.y; vr[14]=v3.z; vr[15]=v3.w;
        }
        float cnt = 0.f, velsq = 0.f, bce = 0.f;   // thread 0 accumulates
        for (int i = rstart; i < rend; i++){
            const uint4* Kr = (const uint4*)(Kh + (size_t)i * MPTS);
            uint4 ka = Kr[t], kb = Kr[256 + t];
            float kf[16];
            cvt16(ka, kb, kf);
            float m = -1.f; int mi = 0;
            #pragma unroll
            for (int c = 0; c < 16; c++){
                float p = kf[c] * vr[c];
                int j = (c < 8) ? (8*t + c) : (2048 + 8*t + c - 8);
                if (p > m){ m = p; mi = j; }
            }
            #pragma unroll
            for (int o = 16; o; o >>= 1){
                float om = __shfl_xor_sync(0xffffffffu, m, o);
                int   oi = __shfl_xor_sync(0xffffffffu, mi, o);
                if (om > m || (om == m && oi < mi)){ m = om; mi = oi; }
            }
            if (lane == 0){ smx[warp] = m; smi[warp] = mi; }
            __syncthreads();
            if (t == 0){
                #pragma unroll
                for (int w = 1; w < 8; w++){
                    if (smx[w] > m || (smx[w] == m && smi[w] < mi)){
                        m = smx[w]; mi = smi[w];
                    }
                }
                float p = g_u[slot][i] * m;
                float a_i = al[i];
                float sp = fmaxf(a_i, 0.f) + log1pf(expf(-fabsf(a_i)));
                bce += sp;
                if (p > SURV_THRESH){
                    cnt += 1.f;
                    bce -= a_i;
                    #pragma unroll
                    for (int d = 0; d < 3; d++){
                        float vt = xg[3*mi + d] - x0[3*i + d];
                        float df = vp[3*i + d] - vt;
                        velsq = fmaf(df, df, velsq);
                    }
                }
            }
            __syncthreads();
        }
        if (t == 0){
            g_loss[b0 + slot][blk][0] = cnt;
            g_loss[b0 + slot][blk][1] = velsq;
            g_loss[b0 + slot][blk][2] = bce;
        }
    }
}

// ---------------------------------------------------------------------------
// Final reduction; also resets the barrier counters for the next replay
// (counters start at 0 from static init; every kernel_launch ends here).
__global__ void __launch_bounds__(NT) k_loss(float* __restrict__ out){
    int t = threadIdx.x;
    if (t < NSLOTS) g_bar[t].c = 0u;
    float cnt = 0.f, velsq = 0.f, bce = 0.f;
    for (int idx = t; idx < NBATCH * GB; idx += NT){
        int b = idx / GB, p = idx % GB;
        cnt   += g_loss[b][p][0];
        velsq += g_loss[b][p][1];
        bce   += g_loss[b][p][2];
    }
    cnt = warpSum(cnt); velsq = warpSum(velsq); bce = warpSum(bce);
    __shared__ float sc[8], sv[8], sb2[8];
    if ((t & 31) == 0){ sc[t>>5] = cnt; sv[t>>5] = velsq; sb2[t>>5] = bce; }
    __syncthreads();
    if (t == 0){
        float C = 0.f, V = 0.f, Bc = 0.f;
        #pragma unroll
        for (int w = 0; w < 8; w++){ C += sc[w]; V += sv[w]; Bc += sb2[w]; }
        float denom = fmaxf(C, 1.f);
        out[0] = V / denom + Bc / (float)(NBATCH * MPTS);
    }
}

// ---------------------------------------------------------------------------
extern "C" void kernel_launch(void* const* d_in, const int* in_sizes, int n_in,
                              void* d_out, int out_size){
    const float* x0 = (const float*)d_in[0];   // (B, M, 3)
    const float* xg = (const float*)d_in[1];   // (B, K, 3)
    const float* vp = (const float*)d_in[2];   // (B, M, 3)
    const float* al = (const float*)d_in[3];   // (B, M, 1)
    (void)in_sizes; (void)n_in; (void)out_size;

    for (int l = 0; l < NBATCH / NSLOTS; l++){
        int b0 = l * NSLOTS;
        k_persist<<<GRID, NT>>>(x0 + (size_t)b0 * MPTS * 3,
                                xg + (size_t)b0 * MPTS * 3,
                                vp + (size_t)b0 * MPTS * 3,
                                al + (size_t)b0 * MPTS,
                                b0, (unsigned)(l * NBARS * GB));
    }
    k_loss<<<1, NT>>>((float*)d_out);
}